// round 6
// baseline (speedup 1.0000x reference)
#include <cuda_runtime.h>
#include <cstdint>

// Constants from the reference
#define EPS     1e-10f
#define B_CONST (1.0f + 0.1f + 0.05f)   // 1.15
#define BR      (1.0f + 0.1f - 0.05f)   // 1.05
#define HW      (512 * 512)

#define CHUNK   512                     // elements per TMA stage
#define NTHREADS 256

// Packed table: .x = v, .y = 1/(v+EPS). One 8B gather returns both values.
__device__ float2 g_vv[HW];

// ---------------------------------------------------------------------------
// Vectorized table build: 4 pixels per thread, float4 loads/stores.
__global__ void __launch_bounds__(256) build_v_kernel(const float4* __restrict__ vin4,
                                                      float* __restrict__ out) {
    int t = blockIdx.x * blockDim.x + threadIdx.x;
    if (t < HW / 4) {
        float4 a = vin4[t];
        float4 b = vin4[t + HW / 4];
        float4 c = vin4[t + 2 * (HW / 4)];
        float4* dst = reinterpret_cast<float4*>(g_vv);

        float v0 = ((a.x + b.x + c.x) * (1.0f/3.0f) * 255.0f + 1.0f) * (1.0f/256.0f);
        float v1 = ((a.y + b.y + c.y) * (1.0f/3.0f) * 255.0f + 1.0f) * (1.0f/256.0f);
        float v2 = ((a.z + b.z + c.z) * (1.0f/3.0f) * 255.0f + 1.0f) * (1.0f/256.0f);
        float v3 = ((a.w + b.w + c.w) * (1.0f/3.0f) * 255.0f + 1.0f) * (1.0f/256.0f);

        dst[2 * t + 0] = make_float4(v0, __frcp_rn(v0 + EPS), v1, __frcp_rn(v1 + EPS));
        dst[2 * t + 1] = make_float4(v2, __frcp_rn(v2 + EPS), v3, __frcp_rn(v3 + EPS));
    }
    if (t == 0) out[0] = 0.0f;
}

// ---------------------------------------------------------------------------
// PTX helpers
__device__ __forceinline__ uint32_t smem_u32(const void* p) {
    return (uint32_t)__cvta_generic_to_shared(p);
}
__device__ __forceinline__ void mbar_init(uint32_t mbar, uint32_t count) {
    asm volatile("mbarrier.init.shared.b64 [%0], %1;" :: "r"(mbar), "r"(count) : "memory");
}
__device__ __forceinline__ void mbar_expect_tx(uint32_t mbar, uint32_t bytes) {
    asm volatile("mbarrier.arrive.expect_tx.shared.b64 _, [%0], %1;"
                 :: "r"(mbar), "r"(bytes) : "memory");
}
__device__ __forceinline__ void mbar_wait(uint32_t mbar, uint32_t parity) {
    uint32_t done;
    asm volatile(
        "{\n\t.reg .pred p;\n\t"
        "mbarrier.try_wait.parity.acquire.cta.shared::cta.b64 p, [%1], %2;\n\t"
        "selp.b32 %0, 1, 0, p;\n\t}"
        : "=r"(done) : "r"(mbar), "r"(parity) : "memory");
    if (!done) {
        asm volatile(
            "{\n\t.reg .pred P1;\n\t"
            "WL_%=:\n\t"
            "mbarrier.try_wait.parity.acquire.cta.shared::cta.b64 P1, [%0], %1, 0x989680;\n\t"
            "@P1 bra.uni WD_%=;\n\t"
            "bra.uni WL_%=;\n\t"
            "WD_%=:\n\t}"
            :: "r"(mbar), "r"(parity) : "memory");
    }
}
// 1-D bulk TMA: global -> shared, completion via mbarrier tx-bytes.
__device__ __forceinline__ void tma_bulk_1d(uint32_t smem_dst, const void* gmem_src,
                                            uint32_t bytes, uint32_t mbar) {
    asm volatile(
        "cp.async.bulk.shared::cluster.global.mbarrier::complete_tx::bytes [%0], [%1], %2, [%3];"
        :: "r"(smem_dst), "l"(gmem_src), "r"(bytes), "r"(mbar) : "memory");
}

// ---------------------------------------------------------------------------
// Loss kernel: streaming data arrives via TMA into double-buffered SMEM
// (off the L1tex wavefront path); L1tex services only the 2 gathers/element.
__global__ void __launch_bounds__(NTHREADS) whdr_loss_kernel(
    const int4*  __restrict__ coords,
    const int*   __restrict__ darker,
    const float* __restrict__ weights,
    float* __restrict__ out,
    int n)
{
    __shared__ alignas(16) int4  s_coords [2][CHUNK];
    __shared__ alignas(16) int   s_darker [2][CHUNK];
    __shared__ alignas(16) float s_weights[2][CHUNK];
    __shared__ alignas(8)  unsigned long long s_mbar[2];

    const float inv_b = 1.0f / B_CONST;
    const float bl    = 1.0f / BR;
    const float inv_n = 1.0f / (float)n;

    int tid = threadIdx.x;
    uint32_t mb0 = smem_u32(&s_mbar[0]);
    uint32_t mb1 = smem_u32(&s_mbar[1]);

    if (tid == 0) { mbar_init(mb0, 1); mbar_init(mb1, 1); }
    __syncthreads();

    const int nchunks = n / CHUNK;
    const uint32_t TX_BYTES = CHUNK * 16u + CHUNK * 4u + CHUNK * 4u;  // 12288

    float acc = 0.0f;

    // Prologue: issue first chunk into slot 0.
    int c0 = blockIdx.x;
    if (c0 < nchunks && tid == 0) {
        mbar_expect_tx(mb0, TX_BYTES);
        tma_bulk_1d(smem_u32(&s_coords [0][0]), coords  + (size_t)c0 * CHUNK, CHUNK * 16u, mb0);
        tma_bulk_1d(smem_u32(&s_darker [0][0]), darker  + (size_t)c0 * CHUNK, CHUNK * 4u,  mb0);
        tma_bulk_1d(smem_u32(&s_weights[0][0]), weights + (size_t)c0 * CHUNK, CHUNK * 4u,  mb0);
    }

    int k = 0;
    for (int c = c0; c < nchunks; c += gridDim.x, k++) {
        int slot = k & 1;
        uint32_t mb = slot ? mb1 : mb0;

        // Issue next chunk into the other slot (free since iteration k-1 + bar).
        int cnext = c + gridDim.x;
        if (cnext < nchunks && tid == 0) {
            uint32_t mbn = (slot ^ 1) ? mb1 : mb0;
            mbar_expect_tx(mbn, TX_BYTES);
            tma_bulk_1d(smem_u32(&s_coords [slot ^ 1][0]), coords  + (size_t)cnext * CHUNK, CHUNK * 16u, mbn);
            tma_bulk_1d(smem_u32(&s_darker [slot ^ 1][0]), darker  + (size_t)cnext * CHUNK, CHUNK * 4u,  mbn);
            tma_bulk_1d(smem_u32(&s_weights[slot ^ 1][0]), weights + (size_t)cnext * CHUNK, CHUNK * 4u,  mbn);
        }

        mbar_wait(mb, (k >> 1) & 1);

        // Process CHUNK elements: 2 per thread, stride NTHREADS (conflict-free LDS).
        #pragma unroll
        for (int j = 0; j < CHUNK / NTHREADS; j++) {
            int e = tid + j * NTHREADS;
            int4  cc = s_coords [slot][e];
            int   d  = s_darker [slot][e];
            float w  = s_weights[slot][e];

            int i1 = (cc.y << 9) | cc.x;
            int i2 = (cc.w << 9) | cc.z;

            float2 p1 = __ldg(&g_vv[i1]);
            float2 p2 = __ldg(&g_vv[i2]);

            float ratio     = p1.x * p2.y;
            float ratio_inv = p2.x * p1.y;

            float l1 = (ratio > inv_b)   ? (ratio - inv_b + (B_CONST - ratio_inv)) : 0.0f;
            float l2 = (ratio < B_CONST) ? (B_CONST - ratio + (ratio_inv - inv_b)) : 0.0f;
            float l0 = (ratio > BR) ? (ratio - BR + (bl - ratio_inv))
                     : ((ratio < bl) ? (bl - ratio + (ratio_inv - BR)) : 0.0f);

            float per = (d == 1) ? l1 : ((d == 2) ? l2 : l0);
            acc += w * per;
        }

        __syncthreads();   // all reads of this slot done before it is re-issued
    }

    // Remainder (n % CHUNK), handled with direct loads by the whole grid.
    int rem_base = nchunks * CHUNK;
    for (int i = rem_base + blockIdx.x * blockDim.x + tid; i < n;
         i += gridDim.x * blockDim.x) {
        int4 cc = coords[i];
        float2 p1 = __ldg(&g_vv[(cc.y << 9) | cc.x]);
        float2 p2 = __ldg(&g_vv[(cc.w << 9) | cc.z]);
        float ratio     = p1.x * p2.y;
        float ratio_inv = p2.x * p1.y;
        float l1 = (ratio > inv_b)   ? (ratio - inv_b + (B_CONST - ratio_inv)) : 0.0f;
        float l2 = (ratio < B_CONST) ? (B_CONST - ratio + (ratio_inv - inv_b)) : 0.0f;
        float l0 = (ratio > BR) ? (ratio - BR + (bl - ratio_inv))
                 : ((ratio < bl) ? (bl - ratio + (ratio_inv - BR)) : 0.0f);
        int d = darker[i];
        acc += weights[i] * ((d == 1) ? l1 : ((d == 2) ? l2 : l0));
    }

    // Warp reduction
    #pragma unroll
    for (int off = 16; off > 0; off >>= 1)
        acc += __shfl_xor_sync(0xffffffffu, acc, off);

    // Block reduction
    __shared__ float warp_sums[8];
    int lane = tid & 31;
    int wid  = tid >> 5;
    if (lane == 0) warp_sums[wid] = acc;
    __syncthreads();
    if (wid == 0) {
        float s = (lane < (NTHREADS >> 5)) ? warp_sums[lane] : 0.0f;
        #pragma unroll
        for (int off = 4; off > 0; off >>= 1)
            s += __shfl_xor_sync(0xffffffffu, s, off);
        if (lane == 0)
            atomicAdd(out, s * inv_n);
    }
}

extern "C" void kernel_launch(void* const* d_in, const int* in_sizes, int n_in,
                              void* d_out, int out_size)
{
    const float4* vin4    = (const float4*)d_in[0];
    const int4*   coords  = (const int4*)d_in[1];
    const int*    darker  = (const int*)d_in[2];
    const float*  weights = (const float*)d_in[3];
    float*        out     = (float*)d_out;

    int n = in_sizes[2];  // darker element count == N

    build_v_kernel<<<(HW / 4 + 255) / 256, 256>>>(vin4, out);

    // 2048 blocks (proven best): 8 TMA chunks per block for N=8388608.
    whdr_loss_kernel<<<2048, NTHREADS>>>(coords, darker, weights, out, n);
}

// round 7
// speedup vs baseline: 1.7881x; 1.7881x over previous
#include <cuda_runtime.h>

// Constants from the reference
#define EPS     1e-10f
#define B_CONST (1.0f + 0.1f + 0.05f)   // 1.15
#define BR      (1.0f + 0.1f - 0.05f)   // 1.05
#define HW      (512 * 512)

// Packed table: .x = v, .y = 1/(v+EPS). One 8B gather returns both values.
__device__ float2 g_vv[HW];

// Vectorized table build: 4 pixels per thread, float4 loads/stores.
__global__ void __launch_bounds__(256) build_v_kernel(const float4* __restrict__ vin4,
                                                      float* __restrict__ out) {
    int t = blockIdx.x * blockDim.x + threadIdx.x;
    if (t < HW / 4) {
        float4 a = vin4[t];
        float4 b = vin4[t + HW / 4];
        float4 c = vin4[t + 2 * (HW / 4)];
        float4* dst = reinterpret_cast<float4*>(g_vv);

        float v0 = ((a.x + b.x + c.x) * (1.0f/3.0f) * 255.0f + 1.0f) * (1.0f/256.0f);
        float v1 = ((a.y + b.y + c.y) * (1.0f/3.0f) * 255.0f + 1.0f) * (1.0f/256.0f);
        float v2 = ((a.z + b.z + c.z) * (1.0f/3.0f) * 255.0f + 1.0f) * (1.0f/256.0f);
        float v3 = ((a.w + b.w + c.w) * (1.0f/3.0f) * 255.0f + 1.0f) * (1.0f/256.0f);

        dst[2 * t + 0] = make_float4(v0, __frcp_rn(v0 + EPS), v1, __frcp_rn(v1 + EPS));
        dst[2 * t + 1] = make_float4(v2, __frcp_rn(v2 + EPS), v3, __frcp_rn(v3 + EPS));
    }
    if (t == 0) out[0] = 0.0f;
}

// R2 loop body verbatim (proven best). Block=128 / grid=4096: same 64 warps/SM,
// smaller per-CTA gather batch -> less cross-CTA L1tex-queue spread, finer
// work-steal granularity. Exact fit: 4096*128*16 = 8388608 = N.
__global__ void __launch_bounds__(128) whdr_loss_kernel(
    const int4*  __restrict__ coords,    // (N,4) int32 as int4: x1,y1,x2,y2
    const int*   __restrict__ darker,    // (N,)
    const float* __restrict__ weights,   // (N,)
    float* __restrict__ out,
    int n)
{
    const float inv_b = 1.0f / B_CONST;
    const float bl    = 1.0f / BR;
    const float inv_n = 1.0f / (float)n;

    float acc = 0.0f;

    int stride = gridDim.x * blockDim.x;
    #pragma unroll 4
    for (int i = blockIdx.x * blockDim.x + threadIdx.x; i < n; i += stride) {
        int4 c  = coords[i];
        int  d  = darker[i];
        float w = weights[i];

        int i1 = (c.y << 9) | c.x;   // y1*512 + x1
        int i2 = (c.w << 9) | c.z;   // y2*512 + x2

        float2 p1 = __ldg(&g_vv[i1]);   // (r1, 1/(r1+eps))
        float2 p2 = __ldg(&g_vv[i2]);   // (r2, 1/(r2+eps))

        float ratio     = p1.x * p2.y;  // r1 / (r2 + EPS)
        float ratio_inv = p2.x * p1.y;  // r2 / (r1 + EPS)

        float l1 = (ratio > inv_b)   ? (ratio - inv_b + (B_CONST - ratio_inv)) : 0.0f;
        float l2 = (ratio < B_CONST) ? (B_CONST - ratio + (ratio_inv - inv_b)) : 0.0f;
        float l0 = (ratio > BR) ? (ratio - BR + (bl - ratio_inv))
                 : ((ratio < bl) ? (bl - ratio + (ratio_inv - BR)) : 0.0f);

        float per = (d == 1) ? l1 : ((d == 2) ? l2 : l0);
        acc += w * per;
    }

    // Warp reduction
    #pragma unroll
    for (int off = 16; off > 0; off >>= 1)
        acc += __shfl_xor_sync(0xffffffffu, acc, off);

    // Block reduction (4 warps)
    __shared__ float warp_sums[4];
    int lane = threadIdx.x & 31;
    int wid  = threadIdx.x >> 5;
    if (lane == 0) warp_sums[wid] = acc;
    __syncthreads();
    if (wid == 0) {
        float s = (lane < 4) ? warp_sums[lane] : 0.0f;
        #pragma unroll
        for (int off = 2; off > 0; off >>= 1)
            s += __shfl_xor_sync(0xffffffffu, s, off);
        if (lane == 0)
            atomicAdd(out, s * inv_n);
    }
}

extern "C" void kernel_launch(void* const* d_in, const int* in_sizes, int n_in,
                              void* d_out, int out_size)
{
    const float4* vin4    = (const float4*)d_in[0];
    const int4*   coords  = (const int4*)d_in[1];
    const int*    darker  = (const int*)d_in[2];
    const float*  weights = (const float*)d_in[3];
    float*        out     = (float*)d_out;

    int n = in_sizes[2];  // darker element count == N

    build_v_kernel<<<(HW / 4 + 255) / 256, 256>>>(vin4, out);

    whdr_loss_kernel<<<4096, 128>>>(coords, darker, weights, out, n);
}